// round 6
// baseline (speedup 1.0000x reference)
#include <cuda_runtime.h>

#define FULLM 0xffffffffu

static constexpr int Bc = 8, Nc = 8192, Dc = 32, Sc = 2048, Kc = 32;
static constexpr int Rc = Bc * Sc * Kc;  // 524288 rows

// ---------------- scratch ----------------------------------------------------
__device__ float4 g_xyzw[Bc * Nc];
__device__ int    g_knn[Rc];
__device__ float  g_feat1[(long long)Rc * 64];
__device__ float  g_feat2[(long long)Rc * 64];
__device__ float  g_feat3[(long long)Rc * 128];
__device__ float  g_stats[256];
__device__ float  g_ab[256];

__device__ __forceinline__ unsigned long long pk2(float lo, float hi) {
    unsigned long long r;
    asm("mov.b64 %0, {%1,%2};" : "=l"(r) : "f"(lo), "f"(hi));
    return r;
}
__device__ __forceinline__ void upk2(unsigned long long v, float& lo, float& hi) {
    asm("mov.b64 {%0,%1}, %2;" : "=f"(lo), "=f"(hi) : "l"(v));
}
#define FMA2(acc, a, b) \
    asm("fma.rn.f32x2 %0, %1, %2, %3;" : "=l"(acc) : "l"(a), "l"(b), "l"(acc))

__device__ __forceinline__ unsigned smem_u32(const void* p) {
    unsigned a;
    asm("{ .reg .u64 t; cvta.to.shared.u64 t, %1; cvt.u32.u64 %0, t; }" : "=r"(a) : "l"(p));
    return a;
}
__device__ __forceinline__ unsigned mapa_u32(unsigned addr, int rank) {
    unsigned r;
    asm("mapa.shared::cluster.u32 %0, %1, %2;" : "=r"(r) : "r"(addr), "r"(rank));
    return r;
}
__device__ __forceinline__ void mbar_wait_cluster(unsigned mbar, unsigned parity) {
    asm volatile(
        "{\n\t.reg .pred P;\n\t"
        "WL_%=:\n\t"
        "mbarrier.try_wait.parity.acquire.cluster.shared::cta.b64 P, [%0], %1, 0x989680;\n\t"
        "@P bra.uni WD_%=;\n\t"
        "bra.uni WL_%=;\n\t"
        "WD_%=:\n\t}"
        :: "r"(mbar), "r"(parity) : "memory");
}

// ---------------- kernel 0: pack xyz + squared norm ---------------------------
__global__ void prep_kernel(const float* __restrict__ xyz) {
    int i = blockIdx.x * blockDim.x + threadIdx.x;
    if (i < Bc * Nc) {
        float x = xyz[3 * i + 0], y = xyz[3 * i + 1], z = xyz[3 * i + 2];
        float w = __fadd_rn(__fadd_rn(__fmul_rn(x, x), __fmul_rn(y, y)), __fmul_rn(z, z));
        g_xyzw[i] = make_float4(x, y, z, w);
    }
}

// ---------------- kernel 1: FPS, 4-CTA cluster per batch ----------------------
// Each CTA owns 2048 points (256 thr x 8 pts, packed f32x2 — arithmetic is
// bit-identical to the reference's sum((xyz-p)**2)). Per iteration: local
// block argmax -> broadcast one u64 key (distbits<<32 | ~idx) to all 4 CTAs
// via st.shared::cluster + mbarrier arrive -> every CTA reduces the 4 keys
// and reads the winner's coords from its own full-cloud smem stash.
// Key compare == (max dist, then min index): exact JAX argmax tie-break.
__global__ __launch_bounds__(256) __cluster_dims__(4, 1, 1)
void fps_kernel(const float* __restrict__ xyz, float* __restrict__ out_xyz) {
    const int b = blockIdx.x >> 2;
    const int rank = blockIdx.x & 3;
    const float* X = xyz + (size_t)b * Nc * 3;
    float* O = out_xyz + (size_t)b * Sc * 3;
    const int t = threadIdx.x;
    const int lane = t & 31, w = t >> 5;          // 8 warps

    __shared__ float s_x[Nc * 3];                 // 96KB full-cloud stash
    __shared__ unsigned long long s_wkey[8];      // per-warp keys
    __shared__ unsigned long long s_rkey[2][4];   // per-parity per-rank keys
    __shared__ __align__(8) unsigned long long s_mbar[2];

    for (int i = t; i < Nc * 3; i += 256) s_x[i] = X[i];

    const unsigned a_mb0 = smem_u32(&s_mbar[0]);
    if (t == 0) {
        asm volatile("mbarrier.init.shared.b64 [%0], 4;" :: "r"(a_mb0) : "memory");
        asm volatile("mbarrier.init.shared.b64 [%0], 4;" :: "r"(a_mb0 + 8) : "memory");
    }
    __syncthreads();
    asm volatile("barrier.cluster.arrive.aligned;" ::: "memory");
    asm volatile("barrier.cluster.wait.aligned;" ::: "memory");

    // my 2048 points: thread t owns pbase + 8t .. 8t+7 (ascending by rank/warp)
    const int pbase = rank * 2048;
    unsigned long long xp[4], yp[4], zp[4];
    float dist[8];
#pragma unroll
    for (int j = 0; j < 4; j++) {
        int i0 = pbase + 8 * t + 2 * j;
        xp[j] = pk2(X[3 * i0 + 0], X[3 * i0 + 3]);
        yp[j] = pk2(X[3 * i0 + 1], X[3 * i0 + 4]);
        zp[j] = pk2(X[3 * i0 + 2], X[3 * i0 + 5]);
        dist[2 * j] = 1e10f;
        dist[2 * j + 1] = 1e10f;
    }

    float qx = X[0], qy = X[1], qz = X[2];
    if (rank == 0 && t == 0) { O[0] = qx; O[1] = qy; O[2] = qz; }

    const unsigned a_rk0 = smem_u32(&s_rkey[0][rank]);

    for (int it = 1; it < Sc; ++it) {
        unsigned long long nq_x = pk2(-qx, -qx), nq_y = pk2(-qy, -qy), nq_z = pk2(-qz, -qz);

        float bestf = 0.0f;
#pragma unroll
        for (int j = 0; j < 4; j++) {
            unsigned long long dx, dy, dz, sx, sy, sz, s;
            asm("add.rn.f32x2 %0, %1, %2;" : "=l"(dx) : "l"(xp[j]), "l"(nq_x));
            asm("add.rn.f32x2 %0, %1, %2;" : "=l"(dy) : "l"(yp[j]), "l"(nq_y));
            asm("add.rn.f32x2 %0, %1, %2;" : "=l"(dz) : "l"(zp[j]), "l"(nq_z));
            asm("mul.rn.f32x2 %0, %1, %1;" : "=l"(sx) : "l"(dx));
            asm("mul.rn.f32x2 %0, %1, %1;" : "=l"(sy) : "l"(dy));
            asm("mul.rn.f32x2 %0, %1, %1;" : "=l"(sz) : "l"(dz));
            asm("add.rn.f32x2 %0, %1, %2;" : "=l"(s) : "l"(sx), "l"(sy));
            asm("add.rn.f32x2 %0, %1, %2;" : "=l"(s) : "l"(s), "l"(sz));
            float d0, d1;
            upk2(s, d0, d1);
            float nd0 = fminf(dist[2 * j], d0);
            dist[2 * j] = nd0;
            bestf = fmaxf(bestf, nd0);
            float nd1 = fminf(dist[2 * j + 1], d1);
            dist[2 * j + 1] = nd1;
            bestf = fmaxf(bestf, nd1);
        }
        // warp argmax (value redux, rescan winners for smallest index)
        unsigned bb = __float_as_uint(bestf);          // dists >= 0
        unsigned wmax = __reduce_max_sync(FULLM, bb);
        unsigned cand = 0xffffffffu;
        if (bb == wmax) {
#pragma unroll
            for (int k = 7; k >= 0; k--)
                if (__float_as_uint(dist[k]) == wmax) cand = (unsigned)(pbase + 8 * t + k);
        }
        unsigned widx = __reduce_min_sync(FULLM, cand);
        if (lane == 0) s_wkey[w] = ((unsigned long long)wmax << 32) |
                                   (unsigned long long)(~widx);
        __syncthreads();

        const int p = it & 1;
        if (w == 0) {
            // block reduce over 8 warp keys
            unsigned long long k8 = (lane < 8) ? s_wkey[lane] : 0ull;
            unsigned v = (unsigned)(k8 >> 32);
            unsigned vm = __reduce_max_sync(FULLM, v);
            unsigned ix = (v == vm && lane < 8) ? (unsigned)(k8 & 0xffffffffu) : 0u;
            unsigned nim = __reduce_max_sync(FULLM, ix);   // max ~idx = min idx
            if (lane == 0) {
                unsigned long long key = ((unsigned long long)vm << 32) | nim;
                unsigned a_slot = a_rk0 + (unsigned)(p * 32);  // s_rkey[p][rank]
                unsigned a_bar = a_mb0 + (unsigned)(p * 8);
#pragma unroll
                for (int peer = 0; peer < 4; peer++) {
                    unsigned ra = mapa_u32(a_slot, peer);
                    asm volatile("st.shared::cluster.u64 [%0], %1;"
                                 :: "r"(ra), "l"(key) : "memory");
                }
#pragma unroll
                for (int peer = 0; peer < 4; peer++) {
                    unsigned ma = mapa_u32(a_bar, peer);
                    asm volatile(
                        "mbarrier.arrive.release.cluster.shared::cluster.b64 _, [%0];"
                        :: "r"(ma) : "memory");
                }
            }
        }
        // wait for all 4 CTAs' keys; phase flips once per use of each mbar
        mbar_wait_cluster(a_mb0 + (unsigned)(p * 8), ((unsigned)(it - 1) >> 1) & 1u);

        // decode winner (every warp independently)
        unsigned long long kk = (lane < 4) ? s_rkey[p][lane] : 0ull;
        unsigned v2 = (unsigned)(kk >> 32);
        unsigned vm2 = __reduce_max_sync(FULLM, v2);
        unsigned ix2 = (v2 == vm2 && lane < 4) ? (unsigned)(kk & 0xffffffffu) : 0u;
        unsigned nim2 = __reduce_max_sync(FULLM, ix2);
        int sel = (int)(~nim2) & (Nc - 1);
        qx = s_x[3 * sel + 0];
        qy = s_x[3 * sel + 1];
        qz = s_x[3 * sel + 2];
        if (rank == 0 && t == 0) {
            O[3 * it + 0] = qx; O[3 * it + 1] = qy; O[3 * it + 2] = qz;
        }
    }

    asm volatile("barrier.cluster.arrive.aligned;" ::: "memory");
    asm volatile("barrier.cluster.wait.aligned;" ::: "memory");
}

// ---------------- kernel 2: KNN (top-32 smallest) ----------------------------
__global__ __launch_bounds__(256) void knn_kernel(const float* __restrict__ newxyz) {
    extern __shared__ float4 s_pts[];
    int b = blockIdx.x >> 8;
    int grp = blockIdx.x & 255;
    const float4* P = g_xyzw + (size_t)b * Nc;
    for (int i = threadIdx.x; i < Nc; i += 256) s_pts[i] = P[i];
    __syncthreads();

    int warp = threadIdx.x >> 5, lane = threadIdx.x & 31;
    int s = grp * 8 + warp;
    int bs = b * Sc + s;
    float cx = newxyz[3 * bs], cy = newxyz[3 * bs + 1], cz = newxyz[3 * bs + 2];
    float cn = __fadd_rn(__fadd_rn(__fmul_rn(cx, cx), __fmul_rn(cy, cy)), __fmul_rn(cz, cz));

    float4 p = s_pts[lane];
    float dot = __fadd_rn(__fadd_rn(__fmul_rn(cx, p.x), __fmul_rn(cy, p.y)), __fmul_rn(cz, p.z));
    float kd = __fadd_rn(__fsub_rn(cn, __fmul_rn(2.0f, dot)), p.w);
    int ki = lane;

    float cm = kd;
#pragma unroll
    for (int o = 16; o; o >>= 1) cm = fmaxf(cm, __shfl_xor_sync(FULLM, cm, o));

    for (int base = 32; base < Nc; base += 32) {
        p = s_pts[base + lane];
        dot = __fadd_rn(__fadd_rn(__fmul_rn(cx, p.x), __fmul_rn(cy, p.y)), __fmul_rn(cz, p.z));
        float d = __fadd_rn(__fsub_rn(cn, __fmul_rn(2.0f, dot)), p.w);
        unsigned m = __ballot_sync(FULLM, d < cm);
        while (m) {
            int src = __ffs(m) - 1;
            m &= m - 1;
            float dn = __shfl_sync(FULLM, d, src);
            if (dn < cm) {
                unsigned mm = __ballot_sync(FULLM, kd == cm);
                int vic = __ffs(mm) - 1;
                if (lane == vic) { kd = dn; ki = base + src; }
                float v = kd;
#pragma unroll
                for (int o = 16; o; o >>= 1) v = fmaxf(v, __shfl_xor_sync(FULLM, v, o));
                cm = v;
            }
        }
    }
    g_knn[bs * 32 + lane] = ki;
}

// ---------------- kernel 3: layer-1 conv (gather) -----------------------------
__global__ __launch_bounds__(256) void mlp1_kernel(const float* __restrict__ W,
                                                   const float* __restrict__ Bias,
                                                   const float* __restrict__ pts,
                                                   const float* __restrict__ newxyz) {
    constexpr int CIN = 35, COUT = 64;
    __shared__ float s_w[CIN * COUT];
    __shared__ float s_b[COUT];
    for (int idx = threadIdx.x; idx < CIN * COUT; idx += 256) {
        int o = idx / CIN, c = idx % CIN;
        s_w[c * COUT + o] = W[idx];
    }
    if (threadIdx.x < COUT) s_b[threadIdx.x] = Bias[threadIdx.x];
    __syncthreads();

    int r = blockIdx.x * 128 + (threadIdx.x & 127);
    int ot = (threadIdx.x / 128) * 32;

    float in[CIN];
    {
        int b = r >> 16;
        int rem = r & 65535;
        int s = rem >> 5;
        int n = g_knn[r];
        float4 p = g_xyzw[b * Nc + n];
        int bs = b * Sc + s;
        in[0] = p.x - newxyz[3 * bs + 0];
        in[1] = p.y - newxyz[3 * bs + 1];
        in[2] = p.z - newxyz[3 * bs + 2];
        const float4* pp = (const float4*)(pts + (size_t)(b * Nc + n) * Dc);
#pragma unroll
        for (int q = 0; q < 8; q++) {
            float4 v = pp[q];
            in[3 + 4 * q] = v.x; in[4 + 4 * q] = v.y;
            in[5 + 4 * q] = v.z; in[6 + 4 * q] = v.w;
        }
    }

    float acc[32];
#pragma unroll
    for (int oo = 0; oo < 32; oo++) acc[oo] = s_b[ot + oo];
#pragma unroll
    for (int c = 0; c < CIN; c++) {
        float v = in[c];
        const float4* wr = (const float4*)(s_w + c * COUT + ot);
#pragma unroll
        for (int o4 = 0; o4 < 8; o4++) {
            float4 wv = wr[o4];
            acc[4 * o4 + 0] = fmaf(v, wv.x, acc[4 * o4 + 0]);
            acc[4 * o4 + 1] = fmaf(v, wv.y, acc[4 * o4 + 1]);
            acc[4 * o4 + 2] = fmaf(v, wv.z, acc[4 * o4 + 2]);
            acc[4 * o4 + 3] = fmaf(v, wv.w, acc[4 * o4 + 3]);
        }
    }
#pragma unroll
    for (int oo = 0; oo < 32; oo++) g_feat1[(size_t)(ot + oo) * Rc + r] = acc[oo];
}

// ---------------- layers 2/3: register-tiled, f32x2, fused BN-stats -----------
template <int LAYER>
__global__ __launch_bounds__(256) void mlp23_kernel(const float* __restrict__ W,
                                                    const float* __restrict__ Bias) {
    constexpr int CIN = 64;
    constexpr int COUT = (LAYER == 3) ? 128 : 64;
    constexpr int TG = COUT / 16;
    constexpr int RPB = (8 / TG) * 128;

    const float* fin = (LAYER == 2) ? g_feat1 : g_feat2;
    float* fout = (LAYER == 2) ? g_feat2 : g_feat3;

    __shared__ __align__(16) float s_w[CIN * COUT];
    __shared__ float s_b[COUT];
    __shared__ float s_a[CIN], s_cc[CIN];

    for (int idx = threadIdx.x; idx < CIN * COUT; idx += 256) {
        int o = idx / CIN, c = idx % CIN;
        s_w[c * COUT + o] = W[idx];
    }
    if (threadIdx.x < COUT) s_b[threadIdx.x] = Bias[threadIdx.x];
    if (threadIdx.x < CIN) {
        s_a[threadIdx.x] = g_ab[threadIdx.x];
        s_cc[threadIdx.x] = g_ab[CIN + threadIdx.x];
    }
    __syncthreads();

    int w = threadIdx.x >> 5, lane = threadIdx.x & 31;
    int tile = w % TG, rg = w / TG;
    int row0 = blockIdx.x * RPB + rg * 128 + lane;
    int ot = tile * 16;

    unsigned long long acc2[4][8];
#pragma unroll
    for (int o = 0; o < 8; o++) {
        unsigned long long bv = pk2(s_b[ot + 2 * o], s_b[ot + 2 * o + 1]);
#pragma unroll
        for (int k = 0; k < 4; k++) acc2[k][o] = bv;
    }

#pragma unroll 4
    for (int c = 0; c < CIN; c++) {
        float a = s_a[c], cc = s_cc[c];
        const float* col = fin + (size_t)c * Rc + row0;
        unsigned long long ind[4];
#pragma unroll
        for (int k = 0; k < 4; k++) {
            float iv = fmaxf(fmaf(a, col[32 * k], cc), 0.0f);
            ind[k] = pk2(iv, iv);
        }
        const ulonglong2* wp = (const ulonglong2*)(s_w + c * COUT + ot);
#pragma unroll
        for (int o4 = 0; o4 < 4; o4++) {
            ulonglong2 wv = wp[o4];
#pragma unroll
            for (int k = 0; k < 4; k++) {
                FMA2(acc2[k][2 * o4 + 0], ind[k], wv.x);
                FMA2(acc2[k][2 * o4 + 1], ind[k], wv.y);
            }
        }
    }

#pragma unroll
    for (int o = 0; o < 8; o++) {
        float lo[4], hi[4];
#pragma unroll
        for (int k = 0; k < 4; k++) {
            upk2(acc2[k][o], lo[k], hi[k]);
            fout[(size_t)(ot + 2 * o) * Rc + row0 + 32 * k] = lo[k];
            fout[(size_t)(ot + 2 * o + 1) * Rc + row0 + 32 * k] = hi[k];
        }
        float su0 = (lo[0] + lo[1]) + (lo[2] + lo[3]);
        float su1 = (hi[0] + hi[1]) + (hi[2] + hi[3]);
        float sq0 = 0.0f, sq1 = 0.0f;
#pragma unroll
        for (int k = 0; k < 4; k++) {
            sq0 = fmaf(lo[k], lo[k], sq0);
            sq1 = fmaf(hi[k], hi[k], sq1);
        }
#pragma unroll
        for (int off = 16; off; off >>= 1) {
            su0 += __shfl_xor_sync(FULLM, su0, off);
            su1 += __shfl_xor_sync(FULLM, su1, off);
            sq0 += __shfl_xor_sync(FULLM, sq0, off);
            sq1 += __shfl_xor_sync(FULLM, sq1, off);
        }
        if (lane == 0) {
            atomicAdd(&g_stats[ot + 2 * o], su0);
            atomicAdd(&g_stats[ot + 2 * o + 1], su1);
            atomicAdd(&g_stats[128 + ot + 2 * o], sq0);
            atomicAdd(&g_stats[128 + ot + 2 * o + 1], sq1);
        }
    }
}

// ---------------- BN statistics (layer 1 only) --------------------------------
__global__ void zero_stats() { g_stats[threadIdx.x] = 0.0f; }

__global__ __launch_bounds__(256) void stats_kernel() {
    const float* f = g_feat1;
    int o = blockIdx.x >> 5;
    int ch = blockIdx.x & 31;
    const float4* p = (const float4*)(f + (size_t)o * Rc) + (size_t)ch * (Rc / 32 / 4);
    float s = 0.0f, sq = 0.0f;
    for (int i = threadIdx.x; i < Rc / 32 / 4; i += 256) {
        float4 v = p[i];
        s += v.x + v.y + v.z + v.w;
        sq = fmaf(v.x, v.x, sq);
        sq = fmaf(v.y, v.y, sq);
        sq = fmaf(v.z, v.z, sq);
        sq = fmaf(v.w, v.w, sq);
    }
#pragma unroll
    for (int off = 16; off; off >>= 1) {
        s += __shfl_xor_sync(FULLM, s, off);
        sq += __shfl_xor_sync(FULLM, sq, off);
    }
    __shared__ float sh[16];
    int warp = threadIdx.x >> 5, lane = threadIdx.x & 31;
    if (lane == 0) { sh[warp] = s; sh[8 + warp] = sq; }
    __syncthreads();
    if (threadIdx.x == 0) {
        float ts = 0.0f, tq = 0.0f;
        for (int ww = 0; ww < 8; ww++) { ts += sh[ww]; tq += sh[8 + ww]; }
        atomicAdd(&g_stats[o], ts);
        atomicAdd(&g_stats[128 + o], tq);
    }
}

__global__ void finalize_kernel(const float* __restrict__ g,
                                const float* __restrict__ be, int C) {
    int o = threadIdx.x;
    if (o < C) {
        const float inv = 1.0f / (float)Rc;
        float mu = g_stats[o] * inv;
        float var = g_stats[128 + o] * inv - mu * mu;
        float a = g[o] * rsqrtf(var + 1e-5f);
        g_ab[o] = a;
        g_ab[C + o] = fmaf(-mu, a, be[o]);
    }
}

// ---------------- BN+ReLU+maxpool over K --------------------------------------
__global__ __launch_bounds__(256) void maxpool_kernel(float* __restrict__ outp) {
    int idx = blockIdx.x * 256 + threadIdx.x;
    int o = idx & 127;
    int bs = idx >> 7;
    float a = g_ab[o], c = g_ab[128 + o];
    const float4* p = (const float4*)(g_feat3 + (size_t)o * Rc + (size_t)bs * 32);
    float m = 0.0f;
#pragma unroll
    for (int q = 0; q < 8; q++) {
        float4 v = p[q];
        m = fmaxf(m, fmaf(a, v.x, c));
        m = fmaxf(m, fmaf(a, v.y, c));
        m = fmaxf(m, fmaf(a, v.z, c));
        m = fmaxf(m, fmaf(a, v.w, c));
    }
    outp[idx] = m;
}

// ---------------- launch --------------------------------------------------------
extern "C" void kernel_launch(void* const* d_in, const int* in_sizes, int n_in,
                              void* d_out, int out_size) {
    const float* xyz = (const float*)d_in[0];
    const float* points = (const float*)d_in[1];
    const float* w1 = (const float*)d_in[2];
    const float* b1 = (const float*)d_in[3];
    const float* g1 = (const float*)d_in[4];
    const float* be1 = (const float*)d_in[5];
    const float* w2 = (const float*)d_in[6];
    const float* b2 = (const float*)d_in[7];
    const float* g2 = (const float*)d_in[8];
    const float* be2 = (const float*)d_in[9];
    const float* w3 = (const float*)d_in[10];
    const float* b3 = (const float*)d_in[11];
    const float* g3 = (const float*)d_in[12];
    const float* be3 = (const float*)d_in[13];

    float* out = (float*)d_out;
    float* out_xyz = out;
    float* out_pts = out + (size_t)Bc * Sc * 3;

    prep_kernel<<<(Bc * Nc + 255) / 256, 256>>>(xyz);
    fps_kernel<<<Bc * 4, 256>>>(xyz, out_xyz);   // 4-CTA clusters (compile-time dims)

    cudaFuncSetAttribute(knn_kernel, cudaFuncAttributeMaxDynamicSharedMemorySize,
                         Nc * (int)sizeof(float4));
    knn_kernel<<<Bc * (Sc / 8), 256, Nc * sizeof(float4)>>>(out_xyz);

    // layer 1 (separate stats pass)
    mlp1_kernel<<<Rc / 128, 256>>>(w1, b1, points, out_xyz);
    zero_stats<<<1, 256>>>();
    stats_kernel<<<64 * 32, 256>>>();
    finalize_kernel<<<1, 128>>>(g1, be1, 64);

    // layer 2 (stats fused)
    zero_stats<<<1, 256>>>();
    mlp23_kernel<2><<<Rc / 256, 256>>>(w2, b2);
    finalize_kernel<<<1, 128>>>(g2, be2, 64);

    // layer 3 (stats fused)
    zero_stats<<<1, 256>>>();
    mlp23_kernel<3><<<Rc / 128, 256>>>(w3, b3);
    finalize_kernel<<<1, 128>>>(g3, be3, 128);

    maxpool_kernel<<<(Bc * Sc * 128) / 256, 256>>>(out_pts);
}

// round 11
// speedup vs baseline: 1.7326x; 1.7326x over previous
#include <cuda_runtime.h>

#define FULLM 0xffffffffu

static constexpr int Bc = 8, Nc = 8192, Dc = 32, Sc = 2048, Kc = 32;
static constexpr int Rc = Bc * Sc * Kc;  // 524288 rows

// ---------------- scratch ----------------------------------------------------
__device__ float4 g_xyzw[Bc * Nc];
__device__ int    g_knn[Rc];
__device__ float  g_feat1[(long long)Rc * 64];
__device__ float  g_feat2[(long long)Rc * 64];
__device__ float  g_feat3[(long long)Rc * 128];
__device__ float  g_stats[256];
__device__ float  g_ab[256];

__device__ __forceinline__ unsigned long long pk2(float lo, float hi) {
    unsigned long long r;
    asm("mov.b64 %0, {%1,%2};" : "=l"(r) : "f"(lo), "f"(hi));
    return r;
}
__device__ __forceinline__ void upk2(unsigned long long v, float& lo, float& hi) {
    asm("mov.b64 {%0,%1}, %2;" : "=f"(lo), "=f"(hi) : "l"(v));
}
#define FMA2(acc, a, b) \
    asm("fma.rn.f32x2 %0, %1, %2, %3;" : "=l"(acc) : "l"(a), "l"(b), "l"(acc))

// warp max of a float via one REDUX on signed bits (valid when the max is
// guaranteed non-negative: any negative < any positive in signed-bit order).
__device__ __forceinline__ float warpmax_fast(float x) {
    return __int_as_float(__reduce_max_sync(FULLM, __float_as_int(x)));
}

// ---------------- kernel 0: pack xyz + squared norm ---------------------------
__global__ void prep_kernel(const float* __restrict__ xyz) {
    int i = blockIdx.x * blockDim.x + threadIdx.x;
    if (i < Bc * Nc) {
        float x = xyz[3 * i + 0], y = xyz[3 * i + 1], z = xyz[3 * i + 2];
        float w = __fadd_rn(__fadd_rn(__fmul_rn(x, x), __fmul_rn(y, y)), __fmul_rn(z, z));
        g_xyzw[i] = make_float4(x, y, z, w);
    }
}

// ---------------- kernel 1: farthest point sampling (R5, proven) --------------
__global__ __launch_bounds__(512) void fps_kernel(const float* __restrict__ xyz,
                                                  float* __restrict__ out_xyz) {
    const int b = blockIdx.x;
    const float* X = xyz + (size_t)b * Nc * 3;
    float* O = out_xyz + (size_t)b * Sc * 3;
    const int t = threadIdx.x;
    const int lane = t & 31, w = t >> 5;

    __shared__ float s_x[Nc * 3];                 // 96KB point stash
    __shared__ unsigned s_wval[2][16];
    __shared__ unsigned s_widx[2][16];

    for (int i = t; i < Nc * 3; i += 512) s_x[i] = X[i];

    unsigned long long xp[8], yp[8], zp[8];
    float dist[16];
#pragma unroll
    for (int j = 0; j < 8; j++) {
        int i0 = 16 * t + 2 * j;
        xp[j] = pk2(X[3 * i0 + 0], X[3 * i0 + 3]);
        yp[j] = pk2(X[3 * i0 + 1], X[3 * i0 + 4]);
        zp[j] = pk2(X[3 * i0 + 2], X[3 * i0 + 5]);
        dist[2 * j] = 1e10f;
        dist[2 * j + 1] = 1e10f;
    }

    float qx = X[0], qy = X[1], qz = X[2];
    if (t == 0) { O[0] = qx; O[1] = qy; O[2] = qz; }
    __syncthreads();

    for (int it = 1; it < Sc; ++it) {
        unsigned long long nq_x = pk2(-qx, -qx), nq_y = pk2(-qy, -qy), nq_z = pk2(-qz, -qz);

        float bestf = 0.0f;
#pragma unroll
        for (int j = 0; j < 8; j++) {
            unsigned long long dx, dy, dz, sx, sy, sz, s;
            asm("add.rn.f32x2 %0, %1, %2;" : "=l"(dx) : "l"(xp[j]), "l"(nq_x));
            asm("add.rn.f32x2 %0, %1, %2;" : "=l"(dy) : "l"(yp[j]), "l"(nq_y));
            asm("add.rn.f32x2 %0, %1, %2;" : "=l"(dz) : "l"(zp[j]), "l"(nq_z));
            asm("mul.rn.f32x2 %0, %1, %1;" : "=l"(sx) : "l"(dx));
            asm("mul.rn.f32x2 %0, %1, %1;" : "=l"(sy) : "l"(dy));
            asm("mul.rn.f32x2 %0, %1, %1;" : "=l"(sz) : "l"(dz));
            asm("add.rn.f32x2 %0, %1, %2;" : "=l"(s) : "l"(sx), "l"(sy));
            asm("add.rn.f32x2 %0, %1, %2;" : "=l"(s) : "l"(s), "l"(sz));
            float d0, d1;
            upk2(s, d0, d1);
            float nd0 = fminf(dist[2 * j], d0);
            dist[2 * j] = nd0;
            bestf = fmaxf(bestf, nd0);
            float nd1 = fminf(dist[2 * j + 1], d1);
            dist[2 * j + 1] = nd1;
            bestf = fmaxf(bestf, nd1);
        }
        unsigned bb = __float_as_uint(bestf);              // dists >= 0
        unsigned wmax = __reduce_max_sync(FULLM, bb);
        unsigned cand = 0xffffffffu;
        if (bb == wmax) {
#pragma unroll
            for (int k = 15; k >= 0; k--)
                if (__float_as_uint(dist[k]) == wmax) cand = (unsigned)(16 * t + k);
        }
        unsigned widx = __reduce_min_sync(FULLM, cand);
        int p = it & 1;
        if (lane == 0) { s_wval[p][w] = wmax; s_widx[p][w] = widx; }
        __syncthreads();
        unsigned v = (lane < 16) ? s_wval[p][lane] : 0u;
        unsigned m2 = __reduce_max_sync(FULLM, v);
        unsigned msk = __ballot_sync(FULLM, (lane < 16) && (v == m2));
        int srcw = __ffs(msk) - 1;                          // lowest warp = smallest idx
        int sel = (int)s_widx[p][srcw];
        qx = s_x[3 * sel + 0];
        qy = s_x[3 * sel + 1];
        qz = s_x[3 * sel + 2];
        if (t == 0) { O[3 * it + 0] = qx; O[3 * it + 1] = qy; O[3 * it + 2] = qz; }
    }
}

// ---------------- kernel 2: KNN (top-32 smallest) ----------------------------
// 512 threads = 16 centroid-warps sharing one 128KB stage. Max recompute via
// one REDUX on signed bits instead of a 5-shfl chain.
__global__ __launch_bounds__(512) void knn_kernel(const float* __restrict__ newxyz) {
    extern __shared__ float4 s_pts[];
    int b = blockIdx.x >> 7;        // 128 groups per batch
    int grp = blockIdx.x & 127;
    const float4* P = g_xyzw + (size_t)b * Nc;
    for (int i = threadIdx.x; i < Nc; i += 512) s_pts[i] = P[i];
    __syncthreads();

    int warp = threadIdx.x >> 5, lane = threadIdx.x & 31;
    int s = grp * 16 + warp;
    int bs = b * Sc + s;
    float cx = newxyz[3 * bs], cy = newxyz[3 * bs + 1], cz = newxyz[3 * bs + 2];
    float cn = __fadd_rn(__fadd_rn(__fmul_rn(cx, cx), __fmul_rn(cy, cy)), __fmul_rn(cz, cz));

    float4 p = s_pts[lane];
    float dot = __fadd_rn(__fadd_rn(__fmul_rn(cx, p.x), __fmul_rn(cy, p.y)), __fmul_rn(cz, p.z));
    float kd = __fadd_rn(__fsub_rn(cn, __fmul_rn(2.0f, dot)), p.w);
    int ki = lane;

    float cm = warpmax_fast(kd);

    for (int base = 32; base < Nc; base += 32) {
        p = s_pts[base + lane];
        dot = __fadd_rn(__fadd_rn(__fmul_rn(cx, p.x), __fmul_rn(cy, p.y)), __fmul_rn(cz, p.z));
        float d = __fadd_rn(__fsub_rn(cn, __fmul_rn(2.0f, dot)), p.w);
        unsigned m = __ballot_sync(FULLM, d < cm);
        while (m) {
            int src = __ffs(m) - 1;
            m &= m - 1;
            float dn = __shfl_sync(FULLM, d, src);
            if (dn < cm) {
                unsigned mm = __ballot_sync(FULLM, kd == cm);
                int vic = __ffs(mm) - 1;
                if (lane == vic) { kd = dn; ki = base + src; }
                cm = warpmax_fast(kd);
            }
        }
    }
    g_knn[bs * 32 + lane] = ki;
}

// ---------------- kernel 3: layer-1 conv, 2 rows x 16 outs per thread ---------
// Each weight LDS.128 feeds two rows; 16-out tiles need 4 loads per channel
// (4x fewer shared-memory reads per row than the 1-row/32-out version).
__global__ __launch_bounds__(256) void mlp1_kernel(const float* __restrict__ W,
                                                   const float* __restrict__ Bias,
                                                   const float* __restrict__ pts,
                                                   const float* __restrict__ newxyz) {
    constexpr int CIN = 35, COUT = 64;
    __shared__ __align__(16) float s_w[CIN * COUT];
    __shared__ float s_b[COUT];
    for (int idx = threadIdx.x; idx < CIN * COUT; idx += 256) {
        int o = idx / CIN, c = idx % CIN;
        s_w[c * COUT + o] = W[idx];
    }
    if (threadIdx.x < COUT) s_b[threadIdx.x] = Bias[threadIdx.x];
    __syncthreads();

    int tile = threadIdx.x >> 6;        // 0..3 -> 16-out tile
    int rid = threadIdx.x & 63;
    int r0 = blockIdx.x * 128 + rid;    // grid = Rc/128
    int r1 = r0 + 64;
    int ot = tile * 16;

    float in0[CIN], in1[CIN];
#pragma unroll
    for (int half = 0; half < 2; half++) {
        int r = half ? r1 : r0;
        float* in = half ? in1 : in0;
        int b = r >> 16;
        int rem = r & 65535;
        int srow = rem >> 5;
        int n = g_knn[r];
        float4 pq = g_xyzw[b * Nc + n];
        int bs = b * Sc + srow;
        in[0] = pq.x - newxyz[3 * bs + 0];
        in[1] = pq.y - newxyz[3 * bs + 1];
        in[2] = pq.z - newxyz[3 * bs + 2];
        const float4* pp = (const float4*)(pts + (size_t)(b * Nc + n) * Dc);
#pragma unroll
        for (int q = 0; q < 8; q++) {
            float4 v = pp[q];
            in[3 + 4 * q] = v.x; in[4 + 4 * q] = v.y;
            in[5 + 4 * q] = v.z; in[6 + 4 * q] = v.w;
        }
    }

    float acc0[16], acc1[16];
#pragma unroll
    for (int oo = 0; oo < 16; oo++) { acc0[oo] = s_b[ot + oo]; acc1[oo] = s_b[ot + oo]; }

#pragma unroll
    for (int c = 0; c < CIN; c++) {
        const float4* wr = (const float4*)(s_w + c * COUT + ot);
        float v0 = in0[c], v1 = in1[c];
#pragma unroll
        for (int o4 = 0; o4 < 4; o4++) {
            float4 wv = wr[o4];
            acc0[4 * o4 + 0] = fmaf(v0, wv.x, acc0[4 * o4 + 0]);
            acc0[4 * o4 + 1] = fmaf(v0, wv.y, acc0[4 * o4 + 1]);
            acc0[4 * o4 + 2] = fmaf(v0, wv.z, acc0[4 * o4 + 2]);
            acc0[4 * o4 + 3] = fmaf(v0, wv.w, acc0[4 * o4 + 3]);
            acc1[4 * o4 + 0] = fmaf(v1, wv.x, acc1[4 * o4 + 0]);
            acc1[4 * o4 + 1] = fmaf(v1, wv.y, acc1[4 * o4 + 1]);
            acc1[4 * o4 + 2] = fmaf(v1, wv.z, acc1[4 * o4 + 2]);
            acc1[4 * o4 + 3] = fmaf(v1, wv.w, acc1[4 * o4 + 3]);
        }
    }
#pragma unroll
    for (int oo = 0; oo < 16; oo++) {
        g_feat1[(size_t)(ot + oo) * Rc + r0] = acc0[oo];
        g_feat1[(size_t)(ot + oo) * Rc + r1] = acc1[oo];
    }
}

// ---------------- layers 2/3: register-tiled, f32x2, fused BN-stats -----------
template <int LAYER>
__global__ __launch_bounds__(256) void mlp23_kernel(const float* __restrict__ W,
                                                    const float* __restrict__ Bias) {
    constexpr int CIN = 64;
    constexpr int COUT = (LAYER == 3) ? 128 : 64;
    constexpr int TG = COUT / 16;
    constexpr int RPB = (8 / TG) * 128;

    const float* fin = (LAYER == 2) ? g_feat1 : g_feat2;
    float* fout = (LAYER == 2) ? g_feat2 : g_feat3;

    __shared__ __align__(16) float s_w[CIN * COUT];
    __shared__ float s_b[COUT];
    __shared__ float s_a[CIN], s_cc[CIN];

    for (int idx = threadIdx.x; idx < CIN * COUT; idx += 256) {
        int o = idx / CIN, c = idx % CIN;
        s_w[c * COUT + o] = W[idx];
    }
    if (threadIdx.x < COUT) s_b[threadIdx.x] = Bias[threadIdx.x];
    if (threadIdx.x < CIN) {
        s_a[threadIdx.x] = g_ab[threadIdx.x];
        s_cc[threadIdx.x] = g_ab[CIN + threadIdx.x];
    }
    __syncthreads();

    int w = threadIdx.x >> 5, lane = threadIdx.x & 31;
    int tile = w % TG, rg = w / TG;
    int row0 = blockIdx.x * RPB + rg * 128 + lane;
    int ot = tile * 16;

    unsigned long long acc2[4][8];
#pragma unroll
    for (int o = 0; o < 8; o++) {
        unsigned long long bv = pk2(s_b[ot + 2 * o], s_b[ot + 2 * o + 1]);
#pragma unroll
        for (int k = 0; k < 4; k++) acc2[k][o] = bv;
    }

#pragma unroll 4
    for (int c = 0; c < CIN; c++) {
        float a = s_a[c], cc = s_cc[c];
        const float* col = fin + (size_t)c * Rc + row0;
        unsigned long long ind[4];
#pragma unroll
        for (int k = 0; k < 4; k++) {
            float iv = fmaxf(fmaf(a, col[32 * k], cc), 0.0f);
            ind[k] = pk2(iv, iv);
        }
        const ulonglong2* wp = (const ulonglong2*)(s_w + c * COUT + ot);
#pragma unroll
        for (int o4 = 0; o4 < 4; o4++) {
            ulonglong2 wv = wp[o4];
#pragma unroll
            for (int k = 0; k < 4; k++) {
                FMA2(acc2[k][2 * o4 + 0], ind[k], wv.x);
                FMA2(acc2[k][2 * o4 + 1], ind[k], wv.y);
            }
        }
    }

#pragma unroll
    for (int o = 0; o < 8; o++) {
        float lo[4], hi[4];
#pragma unroll
        for (int k = 0; k < 4; k++) {
            upk2(acc2[k][o], lo[k], hi[k]);
            fout[(size_t)(ot + 2 * o) * Rc + row0 + 32 * k] = lo[k];
            fout[(size_t)(ot + 2 * o + 1) * Rc + row0 + 32 * k] = hi[k];
        }
        float su0 = (lo[0] + lo[1]) + (lo[2] + lo[3]);
        float su1 = (hi[0] + hi[1]) + (hi[2] + hi[3]);
        float sq0 = 0.0f, sq1 = 0.0f;
#pragma unroll
        for (int k = 0; k < 4; k++) {
            sq0 = fmaf(lo[k], lo[k], sq0);
            sq1 = fmaf(hi[k], hi[k], sq1);
        }
#pragma unroll
        for (int off = 16; off; off >>= 1) {
            su0 += __shfl_xor_sync(FULLM, su0, off);
            su1 += __shfl_xor_sync(FULLM, su1, off);
            sq0 += __shfl_xor_sync(FULLM, sq0, off);
            sq1 += __shfl_xor_sync(FULLM, sq1, off);
        }
        if (lane == 0) {
            atomicAdd(&g_stats[ot + 2 * o], su0);
            atomicAdd(&g_stats[ot + 2 * o + 1], su1);
            atomicAdd(&g_stats[128 + ot + 2 * o], sq0);
            atomicAdd(&g_stats[128 + ot + 2 * o + 1], sq1);
        }
    }
}

// ---------------- BN statistics (layer 1 only) --------------------------------
__global__ void zero_stats() { g_stats[threadIdx.x] = 0.0f; }

__global__ __launch_bounds__(256) void stats_kernel() {
    const float* f = g_feat1;
    int o = blockIdx.x >> 5;
    int ch = blockIdx.x & 31;
    const float4* p = (const float4*)(f + (size_t)o * Rc) + (size_t)ch * (Rc / 32 / 4);
    float s = 0.0f, sq = 0.0f;
    for (int i = threadIdx.x; i < Rc / 32 / 4; i += 256) {
        float4 v = p[i];
        s += v.x + v.y + v.z + v.w;
        sq = fmaf(v.x, v.x, sq);
        sq = fmaf(v.y, v.y, sq);
        sq = fmaf(v.z, v.z, sq);
        sq = fmaf(v.w, v.w, sq);
    }
#pragma unroll
    for (int off = 16; off; off >>= 1) {
        s += __shfl_xor_sync(FULLM, s, off);
        sq += __shfl_xor_sync(FULLM, sq, off);
    }
    __shared__ float sh[16];
    int warp = threadIdx.x >> 5, lane = threadIdx.x & 31;
    if (lane == 0) { sh[warp] = s; sh[8 + warp] = sq; }
    __syncthreads();
    if (threadIdx.x == 0) {
        float ts = 0.0f, tq = 0.0f;
        for (int ww = 0; ww < 8; ww++) { ts += sh[ww]; tq += sh[8 + ww]; }
        atomicAdd(&g_stats[o], ts);
        atomicAdd(&g_stats[128 + o], tq);
    }
}

__global__ void finalize_kernel(const float* __restrict__ g,
                                const float* __restrict__ be, int C) {
    int o = threadIdx.x;
    if (o < C) {
        const float inv = 1.0f / (float)Rc;
        float mu = g_stats[o] * inv;
        float var = g_stats[128 + o] * inv - mu * mu;
        float a = g[o] * rsqrtf(var + 1e-5f);
        g_ab[o] = a;
        g_ab[C + o] = fmaf(-mu, a, be[o]);
    }
}

// ---------------- BN+ReLU+maxpool over K --------------------------------------
__global__ __launch_bounds__(256) void maxpool_kernel(float* __restrict__ outp) {
    int idx = blockIdx.x * 256 + threadIdx.x;
    int o = idx & 127;
    int bs = idx >> 7;
    float a = g_ab[o], c = g_ab[128 + o];
    const float4* p = (const float4*)(g_feat3 + (size_t)o * Rc + (size_t)bs * 32);
    float m = 0.0f;
#pragma unroll
    for (int q = 0; q < 8; q++) {
        float4 v = p[q];
        m = fmaxf(m, fmaf(a, v.x, c));
        m = fmaxf(m, fmaf(a, v.y, c));
        m = fmaxf(m, fmaf(a, v.z, c));
        m = fmaxf(m, fmaf(a, v.w, c));
    }
    outp[idx] = m;
}

// ---------------- launch --------------------------------------------------------
extern "C" void kernel_launch(void* const* d_in, const int* in_sizes, int n_in,
                              void* d_out, int out_size) {
    const float* xyz = (const float*)d_in[0];
    const float* points = (const float*)d_in[1];
    const float* w1 = (const float*)d_in[2];
    const float* b1 = (const float*)d_in[3];
    const float* g1 = (const float*)d_in[4];
    const float* be1 = (const float*)d_in[5];
    const float* w2 = (const float*)d_in[6];
    const float* b2 = (const float*)d_in[7];
    const float* g2 = (const float*)d_in[8];
    const float* be2 = (const float*)d_in[9];
    const float* w3 = (const float*)d_in[10];
    const float* b3 = (const float*)d_in[11];
    const float* g3 = (const float*)d_in[12];
    const float* be3 = (const float*)d_in[13];

    float* out = (float*)d_out;
    float* out_xyz = out;
    float* out_pts = out + (size_t)Bc * Sc * 3;

    prep_kernel<<<(Bc * Nc + 255) / 256, 256>>>(xyz);
    fps_kernel<<<Bc, 512>>>(xyz, out_xyz);

    cudaFuncSetAttribute(knn_kernel, cudaFuncAttributeMaxDynamicSharedMemorySize,
                         Nc * (int)sizeof(float4));
    knn_kernel<<<Bc * (Sc / 16), 512, Nc * sizeof(float4)>>>(out_xyz);

    // layer 1 (separate stats pass)
    mlp1_kernel<<<Rc / 128, 256>>>(w1, b1, points, out_xyz);
    zero_stats<<<1, 256>>>();
    stats_kernel<<<64 * 32, 256>>>();
    finalize_kernel<<<1, 128>>>(g1, be1, 64);

    // layer 2 (stats fused)
    zero_stats<<<1, 256>>>();
    mlp23_kernel<2><<<Rc / 256, 256>>>(w2, b2);
    finalize_kernel<<<1, 128>>>(g2, be2, 64);

    // layer 3 (stats fused)
    zero_stats<<<1, 256>>>();
    mlp23_kernel<3><<<Rc / 128, 256>>>(w3, b3);
    finalize_kernel<<<1, 128>>>(g3, be3, 128);

    maxpool_kernel<<<(Bc * Sc * 128) / 256, 256>>>(out_pts);
}